// round 5
// baseline (speedup 1.0000x reference)
#include <cuda_runtime.h>

#define FULLMASK 0xffffffffu

namespace {
constexpr int H = 32, T = 512, D = 6, B = 4096;
constexpr int SPW = 8;                       // samples per warp (4 groups x 2)
constexpr int WARPS = 4;
constexpr int TPB = WARPS * 32;              // 128
constexpr int GRID = (B / SPW) / WARPS;      // 128 blocks
constexpr int KTOT = 102;                    // 6 + 32 + 32 + 32
constexpr int KX = 0, KH0 = 6, KI1 = 38, KH1 = 70;
constexpr int SROW = 16;                     // staging stride per k: 4 groups x 4 floats
constexpr int SW_FLOATS = KTOT * 128;        // 13056
constexpr int SB0 = SW_FLOATS;               // bias0 at end of weights
constexpr int SB1 = SW_FLOATS + 128;
constexpr int SFIX = SW_FLOATS + 256;        // 13312
constexpr int STG_X = 0;                     // x staging: 6*SROW = 96
constexpr int STG_H0 = 96;                   // h0: 32*SROW = 512
constexpr int STG_H1 = 608;                  // h1: 32*SROW = 512
constexpr int STG_SZ = 1120;                 // per-warp staging floats
constexpr int SMEM_FLOATS = SFIX + WARPS * STG_SZ;   // 17792
constexpr int SMEM_BYTES = SMEM_FLOATS * 4;          // 71168
}

// weights [k][128], row r = 4*unit + gate, pre-scaled by -log2(e) (-2log2(e) for g gate)
__device__ __align__(16) float g_W[SW_FLOATS];
__device__ __align__(16) float g_B[256];     // [0:128) layer0, [128:256) layer1

__global__ void prep_kernel(const float* __restrict__ Wih0, const float* __restrict__ Whh0,
                            const float* __restrict__ bih0, const float* __restrict__ bhh0,
                            const float* __restrict__ Wih1, const float* __restrict__ Whh1,
                            const float* __restrict__ bih1, const float* __restrict__ bhh1) {
    int r = threadIdx.x;
    if (r >= 128) return;
    int u = r >> 2;
    int g = r & 3;
    int orig = g * H + u;                    // original gate-major row
    const float sc = (g == 2) ? -2.8853900817779268f : -1.4426950408889634f;
    g_B[r]       = (bih0[orig] + bhh0[orig]) * sc;
    g_B[128 + r] = (bih1[orig] + bhh1[orig]) * sc;
#pragma unroll
    for (int k = 0; k < D; k++) g_W[(KX + k) * 128 + r] = Wih0[orig * D + k] * sc;
#pragma unroll
    for (int k = 0; k < H; k++) g_W[(KH0 + k) * 128 + r] = Whh0[orig * H + k] * sc;
#pragma unroll
    for (int k = 0; k < H; k++) g_W[(KI1 + k) * 128 + r] = Wih1[orig * H + k] * sc;
#pragma unroll
    for (int k = 0; k < H; k++) g_W[(KH1 + k) * 128 + r] = Whh1[orig * H + k] * sc;
}

__device__ __forceinline__ void fma2(unsigned long long& acc, unsigned long long a,
                                     unsigned long long b) {
    asm("fma.rn.f32x2 %0, %1, %2, %0;" : "+l"(acc) : "l"(a), "l"(b));
}

// returns 1/(1+2^s)  (= sigmoid(a) when s = -log2(e)*a)
__device__ __forceinline__ float sig2(float s) {
    float e;
    asm("ex2.approx.ftz.f32 %0, %1;" : "=f"(e) : "f"(s));
    float r;
    asm("rcp.approx.ftz.f32 %0, %1;" : "=f"(r) : "f"(1.0f + e));
    return r;
}

// one k-slice: 4 weight LDS.128 (contig 128B across 8 lanes) + 2 dup'd broadcasts + 16 FFMA2
#define KSTEP(KB, KK, BCOFF)                                                           \
    {                                                                                  \
        const float* wr = smem + ((KB) + (KK)) * 128 + p * 4;                          \
        const ulonglong2 w0 = *(const ulonglong2*)(wr);                                \
        const ulonglong2 w1 = *(const ulonglong2*)(wr + 32);                           \
        const ulonglong2 w2 = *(const ulonglong2*)(wr + 64);                           \
        const ulonglong2 w3 = *(const ulonglong2*)(wr + 96);                           \
        const unsigned long long v0 =                                                  \
            *(const unsigned long long*)&stg[(BCOFF) + (KK) * SROW + gq * 4];          \
        const unsigned long long v1 =                                                  \
            *(const unsigned long long*)&stg[(BCOFF) + (KK) * SROW + gq * 4 + 2];      \
        fma2(aIF[0][0], v0, w0.x); fma2(aGO[0][0], v0, w0.y);                          \
        fma2(aIF[1][0], v0, w1.x); fma2(aGO[1][0], v0, w1.y);                          \
        fma2(aIF[2][0], v0, w2.x); fma2(aGO[2][0], v0, w2.y);                          \
        fma2(aIF[3][0], v0, w3.x); fma2(aGO[3][0], v0, w3.y);                          \
        fma2(aIF[0][1], v1, w0.x); fma2(aGO[0][1], v1, w0.y);                          \
        fma2(aIF[1][1], v1, w1.x); fma2(aGO[1][1], v1, w1.y);                          \
        fma2(aIF[2][1], v1, w2.x); fma2(aGO[2][1], v1, w2.y);                          \
        fma2(aIF[3][1], v1, w3.x); fma2(aGO[3][1], v1, w3.y);                          \
    }

#define ACC_INIT(BOFF)                                                                 \
    {                                                                                  \
        const float* bb = smem + (BOFF) + p * 4;                                       \
        const ulonglong2 t0 = *(const ulonglong2*)(bb);                                \
        const ulonglong2 t1 = *(const ulonglong2*)(bb + 32);                           \
        const ulonglong2 t2 = *(const ulonglong2*)(bb + 64);                           \
        const ulonglong2 t3 = *(const ulonglong2*)(bb + 96);                           \
        aIF[0][0] = t0.x; aGO[0][0] = t0.y; aIF[0][1] = t0.x; aGO[0][1] = t0.y;        \
        aIF[1][0] = t1.x; aGO[1][0] = t1.y; aIF[1][1] = t1.x; aGO[1][1] = t1.y;        \
        aIF[2][0] = t2.x; aGO[2][0] = t2.y; aIF[2][1] = t2.x; aGO[2][1] = t2.y;        \
        aIF[3][0] = t3.x; aGO[3][0] = t3.y; aIF[3][1] = t3.x; aGO[3][1] = t3.y;        \
    }

#define ACT(CC, SH)                                                                    \
    {                                                                                  \
        _Pragma("unroll") for (int j = 0; j < 4; j++) {                                \
            _Pragma("unroll") for (int s = 0; s < 2; s++) {                            \
                float si, sf, sg, so;                                                  \
                asm("mov.b64 {%0,%1}, %2;" : "=f"(si), "=f"(sf) : "l"(aIF[j][s]));     \
                asm("mov.b64 {%0,%1}, %2;" : "=f"(sg), "=f"(so) : "l"(aGO[j][s]));     \
                const float iv = sig2(si);                                             \
                const float fv = sig2(sf);                                             \
                const float ov = sig2(so);                                             \
                const float gt = fmaf(2.0f, sig2(sg), -1.0f);                          \
                const float c = fmaf(fv, CC[j][s], iv * gt);                           \
                CC[j][s] = c;                                                          \
                const float tc =                                                       \
                    fmaf(2.0f, sig2(c * -2.8853900817779268f), -1.0f);                 \
                const float hv = ov * tc;                                              \
                const int u = 8 * j + p;                                               \
                *(float2*)&stg[(SH) + u * SROW + gq * 4 + s * 2] =                     \
                    make_float2(hv, hv);                                               \
            }                                                                          \
        }                                                                              \
    }

__global__ void __launch_bounds__(TPB, 1)
lstm_kernel(const float* __restrict__ x,
            const float* __restrict__ gamma,
            const float* __restrict__ beta,
            float* __restrict__ out) {
    extern __shared__ float smem[];

    // cooperative copy: weights + prescaled biases
    {
        const float4* src = (const float4*)g_W;
        float4* dst = (float4*)smem;
        for (int i = threadIdx.x; i < SW_FLOATS / 4; i += TPB) dst[i] = src[i];
        const float4* srcb = (const float4*)g_B;
        for (int i = threadIdx.x; i < 64; i += TPB) dst[SW_FLOATS / 4 + i] = srcb[i];
    }
    const int w = threadIdx.x >> 5;
    const int lane = threadIdx.x & 31;
    float* stg = smem + SFIX + w * STG_SZ;
    for (int i = lane; i < STG_SZ; i += 32) stg[i] = 0.0f;   // h0/h1 start at zero
    __syncthreads();

    const int p = lane & 7;       // unit slot: covers units {p, p+8, p+16, p+24}
    const int gq = lane >> 3;     // sample group: samples {2gq, 2gq+1}
    const int job = blockIdx.x * WARPS + w;
    const int sBase = job * SPW;

    // x streaming: 48 values/step (8 samples x 6 dims); lane carries idx lane and lane+32
    const float* xb = x + (size_t)sBase * (T * D);
    const int s0 = lane / 6, d0 = lane - s0 * 6;
    const int i1 = 32 + lane;
    const int s1 = i1 / 6, d1 = i1 - s1 * 6;
    const float* xp0 = xb + (size_t)s0 * (T * D) + d0;
    const float* xp1 = xb + (size_t)s1 * (T * D) + d1;
    const int xo0 = STG_X + d0 * SROW + s0 * 2;
    const int xo1 = STG_X + d1 * SROW + s1 * 2;
    const bool l16 = lane < 16;
    float xa = xp0[0];
    float xbv = l16 ? xp1[0] : 0.0f;

    float c0[4][2], c1[4][2];
#pragma unroll
    for (int j = 0; j < 4; j++) { c0[j][0] = c0[j][1] = c1[j][0] = c1[j][1] = 0.0f; }

    for (int t = 0; t < T; t++) {
        // publish x(t) duplicated
        *(float2*)&stg[xo0] = make_float2(xa, xa);
        if (l16) *(float2*)&stg[xo1] = make_float2(xbv, xbv);
        __syncwarp();
        // prefetch x(t+1)
        const int tn = (t + 1 < T) ? t + 1 : t;
        xa = xp0[(size_t)tn * D];
        if (l16) xbv = xp1[(size_t)tn * D];

        unsigned long long aIF[4][2], aGO[4][2];

        // ---------------- layer 0 ----------------
        ACC_INIT(SB0);
#pragma unroll
        for (int k = 0; k < D; k++) KSTEP(KX, k, STG_X);
#pragma unroll 8
        for (int k = 0; k < H; k++) KSTEP(KH0, k, STG_H0);
        __syncwarp();
        ACT(c0, STG_H0);
        __syncwarp();

        // ---------------- layer 1 ----------------
        ACC_INIT(SB1);
#pragma unroll 8
        for (int k = 0; k < H; k++) KSTEP(KI1, k, STG_H0);
#pragma unroll 8
        for (int k = 0; k < H; k++) KSTEP(KH1, k, STG_H1);
        __syncwarp();
        ACT(c1, STG_H1);
        __syncwarp();
    }

    // ---------------- LayerNorm over H=32 (lane = hidden unit) ----------------
    const float gam = gamma[lane];
    const float bet = beta[lane];
#pragma unroll
    for (int s = 0; s < SPW; s++) {
        const float v = stg[STG_H1 + lane * SROW + s * 2];
        float sum = v;
#pragma unroll
        for (int off = 16; off > 0; off >>= 1) sum += __shfl_xor_sync(FULLMASK, sum, off);
        const float mu = sum * (1.0f / 32.0f);
        const float dd = v - mu;
        float sq = dd * dd;
#pragma unroll
        for (int off = 16; off > 0; off >>= 1) sq += __shfl_xor_sync(FULLMASK, sq, off);
        const float var = sq * (1.0f / 32.0f);
        out[(size_t)(sBase + s) * H + lane] = fmaf(dd * rsqrtf(var + 1e-5f), gam, bet);
    }
}

extern "C" void kernel_launch(void* const* d_in, const int* in_sizes, int n_in,
                              void* d_out, int out_size) {
    const float* x    = (const float*)d_in[0];
    const float* Wih0 = (const float*)d_in[1];
    const float* Whh0 = (const float*)d_in[2];
    const float* bih0 = (const float*)d_in[3];
    const float* bhh0 = (const float*)d_in[4];
    const float* Wih1 = (const float*)d_in[5];
    const float* Whh1 = (const float*)d_in[6];
    const float* bih1 = (const float*)d_in[7];
    const float* bhh1 = (const float*)d_in[8];
    const float* gam  = (const float*)d_in[9];
    const float* bet  = (const float*)d_in[10];
    float* out = (float*)d_out;

    cudaFuncSetAttribute(lstm_kernel, cudaFuncAttributeMaxDynamicSharedMemorySize, SMEM_BYTES);
    prep_kernel<<<1, 128>>>(Wih0, Whh0, bih0, bhh0, Wih1, Whh1, bih1, bhh1);
    lstm_kernel<<<GRID, TPB, SMEM_BYTES>>>(x, gam, bet, out);
}

// round 6
// speedup vs baseline: 1.3372x; 1.3372x over previous
#include <cuda_runtime.h>

#define FULLMASK 0xffffffffu

namespace {
constexpr int H = 32, T = 512, D = 6, B = 4096;
constexpr int NB = 8;                        // samples per warp
constexpr int WARPS = 4;
constexpr int TPB = WARPS * 32;              // 128
constexpr int GRID = (B / NB) / WARPS;       // 128 blocks
constexpr int KH0 = 6, KI1 = 38, KH1 = 70;   // k-row offsets in weight array
constexpr int SW_FLOATS = 102 * 128;         // 13056 (6+32+32+32 k-rows of 128)
constexpr int HP = 72;                       // h staging stride/sample (64 used, pad)
constexpr int XP = 16;                       // x staging stride/sample (12 used)
constexpr int STG_X = 0;                     // x: 8*16 = 128 floats
constexpr int STG_H0 = 128;                  // h0: 8*72 = 576
constexpr int STG_H1 = 704;                  // h1: 8*72 = 576
constexpr int STG_SZ = 1280;                 // per-warp staging floats
constexpr int SMEM_FLOATS = SW_FLOATS + WARPS * STG_SZ;  // 18176
constexpr int SMEM_BYTES = SMEM_FLOATS * 4;              // 72704
}

// weights [k][128], row r = 4*unit + gate, pre-scaled by -log2(e) (-2log2(e) for g gate)
__device__ __align__(16) float g_W[SW_FLOATS];
__device__ __align__(16) float g_B[256];     // [0:128) layer0, [128:256) layer1

__global__ void prep_kernel(const float* __restrict__ Wih0, const float* __restrict__ Whh0,
                            const float* __restrict__ bih0, const float* __restrict__ bhh0,
                            const float* __restrict__ Wih1, const float* __restrict__ Whh1,
                            const float* __restrict__ bih1, const float* __restrict__ bhh1) {
    int r = threadIdx.x;
    if (r >= 128) return;
    int u = r >> 2;
    int g = r & 3;
    int orig = g * H + u;                    // original gate-major row
    const float sc = (g == 2) ? -2.8853900817779268f : -1.4426950408889634f;
    g_B[r]       = (bih0[orig] + bhh0[orig]) * sc;
    g_B[128 + r] = (bih1[orig] + bhh1[orig]) * sc;
#pragma unroll
    for (int k = 0; k < D; k++) g_W[k * 128 + r] = Wih0[orig * D + k] * sc;
#pragma unroll
    for (int k = 0; k < H; k++) g_W[(KH0 + k) * 128 + r] = Whh0[orig * H + k] * sc;
#pragma unroll
    for (int k = 0; k < H; k++) g_W[(KI1 + k) * 128 + r] = Wih1[orig * H + k] * sc;
#pragma unroll
    for (int k = 0; k < H; k++) g_W[(KH1 + k) * 128 + r] = Whh1[orig * H + k] * sc;
}

__device__ __forceinline__ void fma2(unsigned long long& acc, unsigned long long a,
                                     unsigned long long b) {
    asm("fma.rn.f32x2 %0, %1, %2, %0;" : "+l"(acc) : "l"(a), "l"(b));
}

// returns 1/(1+2^s)  (= sigmoid(a) when s = -log2(e)*a)
__device__ __forceinline__ float sig2(float s) {
    float e;
    asm("ex2.approx.ftz.f32 %0, %1;" : "=f"(e) : "f"(s));
    float r;
    asm("rcp.approx.ftz.f32 %0, %1;" : "=f"(r) : "f"(1.0f + e));
    return r;
}

__global__ void __launch_bounds__(TPB, 1)
lstm_kernel(const float* __restrict__ x,
            const float* __restrict__ gamma,
            const float* __restrict__ beta,
            float* __restrict__ out) {
    extern __shared__ float smem[];

    // cooperative copy of pre-permuted, pre-scaled weights into smem
    {
        const float4* src = (const float4*)g_W;
        float4* dst = (float4*)smem;
        for (int i = threadIdx.x; i < SW_FLOATS / 4; i += TPB) dst[i] = src[i];
    }
    const int w = threadIdx.x >> 5;
    const int lane = threadIdx.x & 31;       // lane = hidden unit
    float* stg = smem + SW_FLOATS + w * STG_SZ;
    for (int i = lane; i < STG_SZ; i += 32) stg[i] = 0.0f;   // h0/h1 start at zero
    __syncthreads();

    const int job = blockIdx.x * WARPS + w;
    const int sBase = job * NB;

    // biases (i,f | g,o packed) stay in registers for the whole sequence
    const ulonglong2 bias0 = *reinterpret_cast<const ulonglong2*>(&g_B[4 * lane]);
    const ulonglong2 bias1 = *reinterpret_cast<const ulonglong2*>(&g_B[128 + 4 * lane]);

    // x streaming: 48 values/step; lane carries flat idx 'lane' and (lane<16) 'lane+32'
    const float* xb = x + (size_t)sBase * (T * D);
    const int s0 = lane / 6, d0 = lane - s0 * 6;
    const int i1 = 32 + lane;
    const int s1 = i1 / 6, d1 = i1 - s1 * 6;
    const float* xp0 = xb + (size_t)s0 * (T * D) + d0;
    const float* xp1 = xb + (size_t)s1 * (T * D) + d1;
    const int xo0 = STG_X + s0 * XP + 2 * d0;
    const int xo1 = STG_X + s1 * XP + 2 * d1;
    const bool l16 = lane < 16;
    float xa = xp0[0];
    float xbv = l16 ? xp1[0] : 0.0f;

    float c0[NB], c1[NB];
#pragma unroll
    for (int s = 0; s < NB; s++) { c0[s] = 0.0f; c1[s] = 0.0f; }

    unsigned long long aIF[NB], aGO[NB];

    // one 2-k chunk: 2 coalesced weight LDS.128 + 8 broadcast LDS.128 + 32 FFMA2
#define CHUNK(KB, KC, SH, STRIDE)                                                      \
    {                                                                                  \
        const ulonglong2 wA =                                                          \
            *(const ulonglong2*)&smem[((KB) + (KC)) * 128 + 4 * lane];                 \
        const ulonglong2 wB =                                                          \
            *(const ulonglong2*)&smem[((KB) + (KC) + 1) * 128 + 4 * lane];             \
        _Pragma("unroll") for (int s = 0; s < NB; s++) {                               \
            const ulonglong2 v =                                                       \
                *(const ulonglong2*)&stg[(SH) + s * (STRIDE) + 2 * (KC)];              \
            fma2(aIF[s], v.x, wA.x); fma2(aGO[s], v.x, wA.y);                          \
            fma2(aIF[s], v.y, wB.x); fma2(aGO[s], v.y, wB.y);                          \
        }                                                                              \
    }

    // activation + duplicated store of h for sample s
#define ACT(CC, SH)                                                                    \
    {                                                                                  \
        _Pragma("unroll") for (int s = 0; s < NB; s++) {                               \
            float si, sf, sg, so;                                                      \
            asm("mov.b64 {%0,%1}, %2;" : "=f"(si), "=f"(sf) : "l"(aIF[s]));            \
            asm("mov.b64 {%0,%1}, %2;" : "=f"(sg), "=f"(so) : "l"(aGO[s]));            \
            const float iv = sig2(si);                                                 \
            const float fv = sig2(sf);                                                 \
            const float ov = sig2(so);                                                 \
            const float gt = fmaf(2.0f, sig2(sg), -1.0f);                              \
            const float c = fmaf(fv, CC[s], iv * gt);                                  \
            CC[s] = c;                                                                 \
            const float tc = fmaf(2.0f, sig2(c * -2.8853900817779268f), -1.0f);        \
            const float hv = ov * tc;                                                  \
            *(float2*)&stg[(SH) + s * HP + 2 * lane] = make_float2(hv, hv);            \
        }                                                                              \
    }

    for (int t = 0; t < T; t++) {
        // publish x(t) duplicated, then prefetch x(t+1)
        *(float2*)&stg[xo0] = make_float2(xa, xa);
        if (l16) *(float2*)&stg[xo1] = make_float2(xbv, xbv);
        __syncwarp();
        const int tn = (t + 1 < T) ? t + 1 : t;
        xa = xp0[(size_t)tn * D];
        if (l16) xbv = xp1[(size_t)tn * D];

        // ---------------- layer 0: x (6 k) + h0 (32 k) ----------------
#pragma unroll
        for (int s = 0; s < NB; s++) { aIF[s] = bias0.x; aGO[s] = bias0.y; }
#pragma unroll
        for (int kc = 0; kc < D; kc += 2) CHUNK(0, kc, STG_X, XP);
#pragma unroll 4
        for (int kc = 0; kc < H; kc += 2) CHUNK(KH0, kc, STG_H0, HP);
        __syncwarp();
        ACT(c0, STG_H0);
        __syncwarp();

        // ---------------- layer 1: h0 (32 k) + h1 (32 k) ----------------
#pragma unroll
        for (int s = 0; s < NB; s++) { aIF[s] = bias1.x; aGO[s] = bias1.y; }
#pragma unroll 4
        for (int kc = 0; kc < H; kc += 2) CHUNK(KI1, kc, STG_H0, HP);
#pragma unroll 4
        for (int kc = 0; kc < H; kc += 2) CHUNK(KH1, kc, STG_H1, HP);
        __syncwarp();
        ACT(c1, STG_H1);
        __syncwarp();
    }

    // ---------------- LayerNorm over H=32 (lane = hidden unit) ----------------
    const float gam = gamma[lane];
    const float bet = beta[lane];
#pragma unroll
    for (int s = 0; s < NB; s++) {
        const float v = stg[STG_H1 + s * HP + 2 * lane];
        float sum = v;
#pragma unroll
        for (int off = 16; off > 0; off >>= 1) sum += __shfl_xor_sync(FULLMASK, sum, off);
        const float mu = sum * (1.0f / 32.0f);
        const float dd = v - mu;
        float sq = dd * dd;
#pragma unroll
        for (int off = 16; off > 0; off >>= 1) sq += __shfl_xor_sync(FULLMASK, sq, off);
        const float var = sq * (1.0f / 32.0f);
        out[(size_t)(sBase + s) * H + lane] = fmaf(dd * rsqrtf(var + 1e-5f), gam, bet);
    }
#undef CHUNK
#undef ACT
}

extern "C" void kernel_launch(void* const* d_in, const int* in_sizes, int n_in,
                              void* d_out, int out_size) {
    const float* x    = (const float*)d_in[0];
    const float* Wih0 = (const float*)d_in[1];
    const float* Whh0 = (const float*)d_in[2];
    const float* bih0 = (const float*)d_in[3];
    const float* bhh0 = (const float*)d_in[4];
    const float* Wih1 = (const float*)d_in[5];
    const float* Whh1 = (const float*)d_in[6];
    const float* bih1 = (const float*)d_in[7];
    const float* bhh1 = (const float*)d_in[8];
    const float* gam  = (const float*)d_in[9];
    const float* bet  = (const float*)d_in[10];
    float* out = (float*)d_out;

    cudaFuncSetAttribute(lstm_kernel, cudaFuncAttributeMaxDynamicSharedMemorySize, SMEM_BYTES);
    prep_kernel<<<1, 128>>>(Wih0, Whh0, bih0, bhh0, Wih1, Whh1, bih1, bhh1);
    lstm_kernel<<<GRID, TPB, SMEM_BYTES>>>(x, gam, bet, out);
}

// round 7
// speedup vs baseline: 1.8523x; 1.3852x over previous
#include <cuda_runtime.h>

#define FULLMASK 0xffffffffu

namespace {
constexpr int H = 32, T = 512, D = 6, B = 4096;
constexpr int NB = 4;                        // samples per warp
constexpr int NJOBS = B / NB;                // 1024 warp-jobs
constexpr int WARPS = 7;
constexpr int TPB = WARPS * 32;              // 224
constexpr int GRID = 148;                    // one block per SM
constexpr int KH0 = 6, KI1 = 38, KH1 = 70;   // k-row offsets in weight array
constexpr int SW_FLOATS = 102 * 128;         // 13056
constexpr int XP = 8;                        // x staging stride/sample
constexpr int HP = 32;                       // h staging stride/sample (undup)
constexpr int STG_X = 0;                     // x: 4*8 = 32 floats
constexpr int STG_H0 = 32;                   // h0: 4*32 = 128
constexpr int STG_H1 = 160;                  // h1: 4*32 = 128
constexpr int STG_SZ = 288;                  // per-warp staging floats
constexpr int SMEM_FLOATS = SW_FLOATS + WARPS * STG_SZ;  // 15072
constexpr int SMEM_BYTES = SMEM_FLOATS * 4;              // 60288
}

// weights [k][128], row r = 4*unit + gate, pre-scaled by -log2(e) (-2log2(e) for g gate)
__device__ __align__(16) float g_W[SW_FLOATS];
__device__ __align__(16) float g_B[256];     // [0:128) layer0, [128:256) layer1

__global__ void prep_kernel(const float* __restrict__ Wih0, const float* __restrict__ Whh0,
                            const float* __restrict__ bih0, const float* __restrict__ bhh0,
                            const float* __restrict__ Wih1, const float* __restrict__ Whh1,
                            const float* __restrict__ bih1, const float* __restrict__ bhh1) {
    int r = threadIdx.x;
    if (r >= 128) return;
    int u = r >> 2;
    int g = r & 3;
    int orig = g * H + u;                    // original gate-major row
    const float sc = (g == 2) ? -2.8853900817779268f : -1.4426950408889634f;
    g_B[r]       = (bih0[orig] + bhh0[orig]) * sc;
    g_B[128 + r] = (bih1[orig] + bhh1[orig]) * sc;
#pragma unroll
    for (int k = 0; k < D; k++) g_W[k * 128 + r] = Wih0[orig * D + k] * sc;
#pragma unroll
    for (int k = 0; k < H; k++) g_W[(KH0 + k) * 128 + r] = Whh0[orig * H + k] * sc;
#pragma unroll
    for (int k = 0; k < H; k++) g_W[(KI1 + k) * 128 + r] = Wih1[orig * H + k] * sc;
#pragma unroll
    for (int k = 0; k < H; k++) g_W[(KH1 + k) * 128 + r] = Whh1[orig * H + k] * sc;
}

__device__ __forceinline__ unsigned long long dup2(float v) {
    unsigned long long r;
    asm("mov.b64 %0, {%1, %1};" : "=l"(r) : "f"(v));
    return r;
}
__device__ __forceinline__ void fma2(unsigned long long& acc, unsigned long long a,
                                     unsigned long long b) {
    asm("fma.rn.f32x2 %0, %1, %2, %0;" : "+l"(acc) : "l"(a), "l"(b));
}

// returns 1/(1+2^s)  (= sigmoid(a) when s = -log2(e)*a)
__device__ __forceinline__ float sig2(float s) {
    float e;
    asm("ex2.approx.ftz.f32 %0, %1;" : "=f"(e) : "f"(s));
    float r;
    asm("rcp.approx.ftz.f32 %0, %1;" : "=f"(r) : "f"(1.0f + e));
    return r;
}

__global__ void __launch_bounds__(TPB, 1)
lstm_kernel(const float* __restrict__ x,
            const float* __restrict__ gamma,
            const float* __restrict__ beta,
            float* __restrict__ out) {
    extern __shared__ float smem[];

    // cooperative copy of pre-permuted, pre-scaled weights into smem
    {
        const float4* src = (const float4*)g_W;
        float4* dst = (float4*)smem;
        for (int i = threadIdx.x; i < SW_FLOATS / 4; i += TPB) dst[i] = src[i];
    }
    const int w = threadIdx.x >> 5;
    const int lane = threadIdx.x & 31;       // lane = hidden unit
    float* stg = smem + SW_FLOATS + w * STG_SZ;
    for (int i = lane; i < STG_SZ; i += 32) stg[i] = 0.0f;   // h0/h1 start at zero
    __syncthreads();

    const int job = w * GRID + (int)blockIdx.x;  // balanced across 148 SMs
    if (job >= NJOBS) return;                    // only __syncwarp below: safe
    const int sBase = job * NB;

    // biases (i,f | g,o packed) stay in registers for the whole sequence
    const ulonglong2 bias0 = *reinterpret_cast<const ulonglong2*>(&g_B[4 * lane]);
    const ulonglong2 bias1 = *reinterpret_cast<const ulonglong2*>(&g_B[128 + 4 * lane]);

    // x streaming: 24 values/step; lanes 0..23 carry one (sample, dim) each
    const float* xb = x + (size_t)sBase * (T * D);
    const int s0 = lane / 6, d0 = lane - s0 * 6;
    const bool xact = lane < 24;
    const float* xp0 = xb + (size_t)s0 * (T * D) + d0;
    const int xo0 = STG_X + s0 * XP + d0;
    float xa = xact ? xp0[0] : 0.0f;

    float c0[NB], c1[NB];
#pragma unroll
    for (int s = 0; s < NB; s++) { c0[s] = 0.0f; c1[s] = 0.0f; }

    unsigned long long aIF[NB], aGO[NB];

    // 4-k chunk: 4 coalesced weight LDS.128 + per-sample 1 broadcast LDS.128
    //            + 4 dup movs + 8 FFMA2
#define CHUNK4(KB, KC, SH, STRIDE)                                                     \
    {                                                                                  \
        const ulonglong2 w0 = *(const ulonglong2*)&smem[((KB) + (KC)) * 128 + 4 * lane]; \
        const ulonglong2 w1 = *(const ulonglong2*)&smem[((KB) + (KC) + 1) * 128 + 4 * lane]; \
        const ulonglong2 w2 = *(const ulonglong2*)&smem[((KB) + (KC) + 2) * 128 + 4 * lane]; \
        const ulonglong2 w3 = *(const ulonglong2*)&smem[((KB) + (KC) + 3) * 128 + 4 * lane]; \
        _Pragma("unroll") for (int s = 0; s < NB; s++) {                               \
            const float4 v = *(const float4*)&stg[(SH) + s * (STRIDE) + (KC)];         \
            const unsigned long long e0 = dup2(v.x);                                   \
            const unsigned long long e1 = dup2(v.y);                                   \
            const unsigned long long e2 = dup2(v.z);                                   \
            const unsigned long long e3 = dup2(v.w);                                   \
            fma2(aIF[s], e0, w0.x); fma2(aGO[s], e0, w0.y);                            \
            fma2(aIF[s], e1, w1.x); fma2(aGO[s], e1, w1.y);                            \
            fma2(aIF[s], e2, w2.x); fma2(aGO[s], e2, w2.y);                            \
            fma2(aIF[s], e3, w3.x); fma2(aGO[s], e3, w3.y);                            \
        }                                                                              \
    }

#define CHUNK2(KB, KC, SH, STRIDE)                                                     \
    {                                                                                  \
        const ulonglong2 w0 = *(const ulonglong2*)&smem[((KB) + (KC)) * 128 + 4 * lane]; \
        const ulonglong2 w1 = *(const ulonglong2*)&smem[((KB) + (KC) + 1) * 128 + 4 * lane]; \
        _Pragma("unroll") for (int s = 0; s < NB; s++) {                               \
            const float2 v = *(const float2*)&stg[(SH) + s * (STRIDE) + (KC)];         \
            const unsigned long long e0 = dup2(v.x);                                   \
            const unsigned long long e1 = dup2(v.y);                                   \
            fma2(aIF[s], e0, w0.x); fma2(aGO[s], e0, w0.y);                            \
            fma2(aIF[s], e1, w1.x); fma2(aGO[s], e1, w1.y);                            \
        }                                                                              \
    }

    // activation + undup store of h (lane = unit): 1 STS.32 per sample
#define ACT(CC, SH)                                                                    \
    {                                                                                  \
        _Pragma("unroll") for (int s = 0; s < NB; s++) {                               \
            float si, sf, sg, so;                                                      \
            asm("mov.b64 {%0,%1}, %2;" : "=f"(si), "=f"(sf) : "l"(aIF[s]));            \
            asm("mov.b64 {%0,%1}, %2;" : "=f"(sg), "=f"(so) : "l"(aGO[s]));            \
            const float iv = sig2(si);                                                 \
            const float fv = sig2(sf);                                                 \
            const float ov = sig2(so);                                                 \
            const float gt = fmaf(2.0f, sig2(sg), -1.0f);                              \
            const float c = fmaf(fv, CC[s], iv * gt);                                  \
            CC[s] = c;                                                                 \
            const float tc = fmaf(2.0f, sig2(c * -2.8853900817779268f), -1.0f);        \
            stg[(SH) + s * HP + lane] = ov * tc;                                       \
        }                                                                              \
    }

    for (int t = 0; t < T; t++) {
        // publish x(t), then prefetch x(t+1)
        if (xact) stg[xo0] = xa;
        __syncwarp();
        const int tn = (t + 1 < T) ? t + 1 : t;
        if (xact) xa = xp0[(size_t)tn * D];

        // ---------------- layer 0: x (6 k) + h0 (32 k) ----------------
#pragma unroll
        for (int s = 0; s < NB; s++) { aIF[s] = bias0.x; aGO[s] = bias0.y; }
        CHUNK4(0, 0, STG_X, XP);
        CHUNK2(0, 4, STG_X, XP);
#pragma unroll
        for (int kc = 0; kc < H; kc += 4) CHUNK4(KH0, kc, STG_H0, HP);
        __syncwarp();
        ACT(c0, STG_H0);
        __syncwarp();

        // ---------------- layer 1: h0 (32 k) + h1 (32 k) ----------------
#pragma unroll
        for (int s = 0; s < NB; s++) { aIF[s] = bias1.x; aGO[s] = bias1.y; }
#pragma unroll
        for (int kc = 0; kc < H; kc += 4) CHUNK4(KI1, kc, STG_H0, HP);
#pragma unroll
        for (int kc = 0; kc < H; kc += 4) CHUNK4(KH1, kc, STG_H1, HP);
        __syncwarp();
        ACT(c1, STG_H1);
        __syncwarp();
    }

    // ---------------- LayerNorm over H=32 (lane = hidden unit) ----------------
    const float gam = gamma[lane];
    const float bet = beta[lane];
#pragma unroll
    for (int s = 0; s < NB; s++) {
        const float v = stg[STG_H1 + s * HP + lane];
        float sum = v;
#pragma unroll
        for (int off = 16; off > 0; off >>= 1) sum += __shfl_xor_sync(FULLMASK, sum, off);
        const float mu = sum * (1.0f / 32.0f);
        const float dd = v - mu;
        float sq = dd * dd;
#pragma unroll
        for (int off = 16; off > 0; off >>= 1) sq += __shfl_xor_sync(FULLMASK, sq, off);
        const float var = sq * (1.0f / 32.0f);
        out[(size_t)(sBase + s) * H + lane] = fmaf(dd * rsqrtf(var + 1e-5f), gam, bet);
    }
#undef CHUNK4
#undef CHUNK2
#undef ACT
}

extern "C" void kernel_launch(void* const* d_in, const int* in_sizes, int n_in,
                              void* d_out, int out_size) {
    const float* x    = (const float*)d_in[0];
    const float* Wih0 = (const float*)d_in[1];
    const float* Whh0 = (const float*)d_in[2];
    const float* bih0 = (const float*)d_in[3];
    const float* bhh0 = (const float*)d_in[4];
    const float* Wih1 = (const float*)d_in[5];
    const float* Whh1 = (const float*)d_in[6];
    const float* bih1 = (const float*)d_in[7];
    const float* bhh1 = (const float*)d_in[8];
    const float* gam  = (const float*)d_in[9];
    const float* bet  = (const float*)d_in[10];
    float* out = (float*)d_out;

    cudaFuncSetAttribute(lstm_kernel, cudaFuncAttributeMaxDynamicSharedMemorySize, SMEM_BYTES);
    prep_kernel<<<1, 128>>>(Wih0, Whh0, bih0, bhh0, Wih1, Whh1, bih1, bhh1);
    lstm_kernel<<<GRID, TPB, SMEM_BYTES>>>(x, gam, bet, out);
}

// round 8
// speedup vs baseline: 1.8983x; 1.0248x over previous
#include <cuda_runtime.h>

#define FULLMASK 0xffffffffu

namespace {
constexpr int H = 32, T = 512, D = 6, B = 4096;
constexpr int NB = 4;                        // samples per warp
constexpr int NJOBS = B / NB;                // 1024 warp-jobs
constexpr int WARPS = 7;
constexpr int TPB = WARPS * 32;              // 224
constexpr int GRID = 148;                    // one block per SM
constexpr int KH0 = 6, KI1 = 38, KH1 = 70;   // k-row offsets in weight array
constexpr int SW_FLOATS = 102 * 128;         // 13056
constexpr int NC = 28;                       // register-cached k-rows (KH1 k=4..31)
constexpr int XP = 8;                        // x staging stride/sample
constexpr int HP = 32;                       // h staging stride/sample (undup)
constexpr int STG_X = 0;                     // x: 4*8 = 32 floats
constexpr int STG_H0 = 32;                   // h0: 4*32 = 128
constexpr int STG_H1 = 160;                  // h1: 4*32 = 128
constexpr int STG_SZ = 288;                  // per-warp staging floats
constexpr int SMEM_FLOATS = SW_FLOATS + WARPS * STG_SZ;  // 15072
constexpr int SMEM_BYTES = SMEM_FLOATS * 4;              // 60288
}

// weights [k][128], row r = 4*unit + gate, pre-scaled by -log2(e) (-2log2(e) for g gate)
__device__ __align__(16) float g_W[SW_FLOATS];
__device__ __align__(16) float g_B[256];     // [0:128) layer0, [128:256) layer1

__global__ void prep_kernel(const float* __restrict__ Wih0, const float* __restrict__ Whh0,
                            const float* __restrict__ bih0, const float* __restrict__ bhh0,
                            const float* __restrict__ Wih1, const float* __restrict__ Whh1,
                            const float* __restrict__ bih1, const float* __restrict__ bhh1) {
    int r = threadIdx.x;
    if (r >= 128) return;
    int u = r >> 2;
    int g = r & 3;
    int orig = g * H + u;                    // original gate-major row
    const float sc = (g == 2) ? -2.8853900817779268f : -1.4426950408889634f;
    g_B[r]       = (bih0[orig] + bhh0[orig]) * sc;
    g_B[128 + r] = (bih1[orig] + bhh1[orig]) * sc;
#pragma unroll
    for (int k = 0; k < D; k++) g_W[k * 128 + r] = Wih0[orig * D + k] * sc;
#pragma unroll
    for (int k = 0; k < H; k++) g_W[(KH0 + k) * 128 + r] = Whh0[orig * H + k] * sc;
#pragma unroll
    for (int k = 0; k < H; k++) g_W[(KI1 + k) * 128 + r] = Wih1[orig * H + k] * sc;
#pragma unroll
    for (int k = 0; k < H; k++) g_W[(KH1 + k) * 128 + r] = Whh1[orig * H + k] * sc;
}

__device__ __forceinline__ unsigned long long dup2(float v) {
    unsigned long long r;
    asm("mov.b64 %0, {%1, %1};" : "=l"(r) : "f"(v));
    return r;
}
__device__ __forceinline__ void fma2(unsigned long long& acc, unsigned long long a,
                                     unsigned long long b) {
    asm("fma.rn.f32x2 %0, %1, %2, %0;" : "+l"(acc) : "l"(a), "l"(b));
}

// returns 1/(1+2^s)  (= sigmoid(a) when s = -log2(e)*a)
__device__ __forceinline__ float sig2(float s) {
    float e;
    asm("ex2.approx.ftz.f32 %0, %1;" : "=f"(e) : "f"(s));
    float r;
    asm("rcp.approx.ftz.f32 %0, %1;" : "=f"(r) : "f"(1.0f + e));
    return r;
}

__global__ void __launch_bounds__(TPB, 1)
lstm_kernel(const float* __restrict__ x,
            const float* __restrict__ gamma,
            const float* __restrict__ beta,
            float* __restrict__ out) {
    extern __shared__ float smem[];

    // cooperative copy of pre-permuted, pre-scaled weights into smem
    {
        const float4* src = (const float4*)g_W;
        float4* dst = (float4*)smem;
        for (int i = threadIdx.x; i < SW_FLOATS / 4; i += TPB) dst[i] = src[i];
    }
    const int w = threadIdx.x >> 5;
    const int lane = threadIdx.x & 31;       // lane = hidden unit
    float* stg = smem + SW_FLOATS + w * STG_SZ;
    for (int i = lane; i < STG_SZ; i += 32) stg[i] = 0.0f;   // h0/h1 start at zero
    __syncthreads();

    const int job = w * GRID + (int)blockIdx.x;  // balanced across 148 SMs
    if (job >= NJOBS) return;                    // only __syncwarp below: safe
    const int sBase = job * NB;

    // biases (i,f | g,o packed) stay in registers for the whole sequence
    const ulonglong2 bias0 = *reinterpret_cast<const ulonglong2*>(&g_B[4 * lane]);
    const ulonglong2 bias1 = *reinterpret_cast<const ulonglong2*>(&g_B[128 + 4 * lane]);

    // register-cached weights: KH1 rows k = 4..31 (28 rows x 16B per lane)
    ulonglong2 wc[NC];
#pragma unroll
    for (int i = 0; i < NC; i++)
        wc[i] = *(const ulonglong2*)&smem[(KH1 + 4 + i) * 128 + 4 * lane];

    // x streaming: 24 values/step; lanes 0..23 carry one (sample, dim) each
    const float* xb = x + (size_t)sBase * (T * D);
    const int s0 = lane / 6, d0 = lane - s0 * 6;
    const bool xact = lane < 24;
    const float* xp0 = xb + (size_t)s0 * (T * D) + d0;
    const int xo0 = STG_X + s0 * XP + d0;
    float xa = xact ? xp0[0] : 0.0f;

    float c0[NB], c1[NB];
#pragma unroll
    for (int s = 0; s < NB; s++) { c0[s] = 0.0f; c1[s] = 0.0f; }

    unsigned long long aIF[NB], aGO[NB];

    // 4-k chunk, weights from smem
#define CHUNK4(KB, KC, SH, STRIDE)                                                     \
    {                                                                                  \
        const ulonglong2 w0 = *(const ulonglong2*)&smem[((KB) + (KC)) * 128 + 4 * lane]; \
        const ulonglong2 w1 = *(const ulonglong2*)&smem[((KB) + (KC) + 1) * 128 + 4 * lane]; \
        const ulonglong2 w2 = *(const ulonglong2*)&smem[((KB) + (KC) + 2) * 128 + 4 * lane]; \
        const ulonglong2 w3 = *(const ulonglong2*)&smem[((KB) + (KC) + 3) * 128 + 4 * lane]; \
        _Pragma("unroll") for (int s = 0; s < NB; s++) {                               \
            const float4 v = *(const float4*)&stg[(SH) + s * (STRIDE) + (KC)];         \
            const unsigned long long e0 = dup2(v.x);                                   \
            const unsigned long long e1 = dup2(v.y);                                   \
            const unsigned long long e2 = dup2(v.z);                                   \
            const unsigned long long e3 = dup2(v.w);                                   \
            fma2(aIF[s], e0, w0.x); fma2(aGO[s], e0, w0.y);                            \
            fma2(aIF[s], e1, w1.x); fma2(aGO[s], e1, w1.y);                            \
            fma2(aIF[s], e2, w2.x); fma2(aGO[s], e2, w2.y);                            \
            fma2(aIF[s], e3, w3.x); fma2(aGO[s], e3, w3.y);                            \
        }                                                                              \
    }

    // 4-k chunk, weights from register cache wc[I0..I0+3], broadcasts from smem
#define CHUNK4R(I0, KC, SH, STRIDE)                                                    \
    {                                                                                  \
        _Pragma("unroll") for (int s = 0; s < NB; s++) {                               \
            const float4 v = *(const float4*)&stg[(SH) + s * (STRIDE) + (KC)];         \
            const unsigned long long e0 = dup2(v.x);                                   \
            const unsigned long long e1 = dup2(v.y);                                   \
            const unsigned long long e2 = dup2(v.z);                                   \
            const unsigned long long e3 = dup2(v.w);                                   \
            fma2(aIF[s], e0, wc[(I0)].x);     fma2(aGO[s], e0, wc[(I0)].y);            \
            fma2(aIF[s], e1, wc[(I0) + 1].x); fma2(aGO[s], e1, wc[(I0) + 1].y);        \
            fma2(aIF[s], e2, wc[(I0) + 2].x); fma2(aGO[s], e2, wc[(I0) + 2].y);        \
            fma2(aIF[s], e3, wc[(I0) + 3].x); fma2(aGO[s], e3, wc[(I0) + 3].y);        \
        }                                                                              \
    }

#define CHUNK2(KB, KC, SH, STRIDE)                                                     \
    {                                                                                  \
        const ulonglong2 w0 = *(const ulonglong2*)&smem[((KB) + (KC)) * 128 + 4 * lane]; \
        const ulonglong2 w1 = *(const ulonglong2*)&smem[((KB) + (KC) + 1) * 128 + 4 * lane]; \
        _Pragma("unroll") for (int s = 0; s < NB; s++) {                               \
            const float2 v = *(const float2*)&stg[(SH) + s * (STRIDE) + (KC)];         \
            const unsigned long long e0 = dup2(v.x);                                   \
            const unsigned long long e1 = dup2(v.y);                                   \
            fma2(aIF[s], e0, w0.x); fma2(aGO[s], e0, w0.y);                            \
            fma2(aIF[s], e1, w1.x); fma2(aGO[s], e1, w1.y);                            \
        }                                                                              \
    }

    // activation + undup store of h (lane = unit): 1 STS.32 per sample
#define ACT(CC, SH)                                                                    \
    {                                                                                  \
        _Pragma("unroll") for (int s = 0; s < NB; s++) {                               \
            float si, sf, sg, so;                                                      \
            asm("mov.b64 {%0,%1}, %2;" : "=f"(si), "=f"(sf) : "l"(aIF[s]));            \
            asm("mov.b64 {%0,%1}, %2;" : "=f"(sg), "=f"(so) : "l"(aGO[s]));            \
            const float iv = sig2(si);                                                 \
            const float fv = sig2(sf);                                                 \
            const float ov = sig2(so);                                                 \
            const float gt = fmaf(2.0f, sig2(sg), -1.0f);                              \
            const float c = fmaf(fv, CC[s], iv * gt);                                  \
            CC[s] = c;                                                                 \
            const float tc = fmaf(2.0f, sig2(c * -2.8853900817779268f), -1.0f);        \
            stg[(SH) + s * HP + lane] = ov * tc;                                       \
        }                                                                              \
    }

    for (int t = 0; t < T; t++) {
        // publish x(t), then prefetch x(t+1)
        if (xact) stg[xo0] = xa;
        __syncwarp();
        const int tn = (t + 1 < T) ? t + 1 : t;
        if (xact) xa = xp0[(size_t)tn * D];

        // ---------------- layer 0: x (6 k) + h0 (32 k) ----------------
#pragma unroll
        for (int s = 0; s < NB; s++) { aIF[s] = bias0.x; aGO[s] = bias0.y; }
        CHUNK4(0, 0, STG_X, XP);
        CHUNK2(0, 4, STG_X, XP);
#pragma unroll
        for (int kc = 0; kc < H; kc += 4) CHUNK4(KH0, kc, STG_H0, HP);
        __syncwarp();
        ACT(c0, STG_H0);
        __syncwarp();

        // ---------------- layer 1: h0 (32 k) + h1 (32 k) ----------------
#pragma unroll
        for (int s = 0; s < NB; s++) { aIF[s] = bias1.x; aGO[s] = bias1.y; }
#pragma unroll
        for (int kc = 0; kc < H; kc += 4) CHUNK4(KI1, kc, STG_H0, HP);
        CHUNK4(KH1, 0, STG_H1, HP);                       // k 0..3 from smem
#pragma unroll
        for (int kc = 4; kc < H; kc += 4)                 // k 4..31 from registers
            CHUNK4R(kc - 4, kc, STG_H1, HP);
        __syncwarp();
        ACT(c1, STG_H1);
        __syncwarp();
    }

    // ---------------- LayerNorm over H=32 (lane = hidden unit) ----------------
    const float gam = gamma[lane];
    const float bet = beta[lane];
#pragma unroll
    for (int s = 0; s < NB; s++) {
        const float v = stg[STG_H1 + s * HP + lane];
        float sum = v;
#pragma unroll
        for (int off = 16; off > 0; off >>= 1) sum += __shfl_xor_sync(FULLMASK, sum, off);
        const float mu = sum * (1.0f / 32.0f);
        const float dd = v - mu;
        float sq = dd * dd;
#pragma unroll
        for (int off = 16; off > 0; off >>= 1) sq += __shfl_xor_sync(FULLMASK, sq, off);
        const float var = sq * (1.0f / 32.0f);
        out[(size_t)(sBase + s) * H + lane] = fmaf(dd * rsqrtf(var + 1e-5f), gam, bet);
    }
#undef CHUNK4
#undef CHUNK4R
#undef CHUNK2
#undef ACT
}

extern "C" void kernel_launch(void* const* d_in, const int* in_sizes, int n_in,
                              void* d_out, int out_size) {
    const float* x    = (const float*)d_in[0];
    const float* Wih0 = (const float*)d_in[1];
    const float* Whh0 = (const float*)d_in[2];
    const float* bih0 = (const float*)d_in[3];
    const float* bhh0 = (const float*)d_in[4];
    const float* Wih1 = (const float*)d_in[5];
    const float* Whh1 = (const float*)d_in[6];
    const float* bih1 = (const float*)d_in[7];
    const float* bhh1 = (const float*)d_in[8];
    const float* gam  = (const float*)d_in[9];
    const float* bet  = (const float*)d_in[10];
    float* out = (float*)d_out;

    cudaFuncSetAttribute(lstm_kernel, cudaFuncAttributeMaxDynamicSharedMemorySize, SMEM_BYTES);
    prep_kernel<<<1, 128>>>(Wih0, Whh0, bih0, bhh0, Wih1, Whh1, bih1, bhh1);
    lstm_kernel<<<GRID, TPB, SMEM_BYTES>>>(x, gam, bet, out);
}